// round 15
// baseline (speedup 1.0000x reference)
#include <cuda_runtime.h>
#include <cuda_bf16.h>
#include <math.h>
#include <stdint.h>

#define KT   50
#define TT   50
#define RHOD 300
#define KP   320
#define VV   20000
#define KP2  20032
#define KCH  2504
#define KSTG 313
#define VP   20096
#define NT   157
#define NT2  (2*NT)
#define MT   20
#define THH  800
#define EHH  200
#define SSRC 10
#define BB   256
#define H1Z  21
#define EMZ  35
#define DELTAF 0.005f
#define LOG_DELTA_F (-5.2983173665480363f)
#define EPSF 1e-6f
#define NVTILE 20
#define NG8  (KP2/8)

// mega_prep block ranges
#define NB_ABF 400
#define NB_BBF 3140
#define NB_CN  2504
#define NB_CW  8764
#define NB_CR  5008
#define NB_CE  2504
#define NB_WH  313
#define NB_HD  157
#define NB_DL  1
#define NB_KA  2500

// mega_gemm ranges
#define GB_BETA 3140
#define GB_ETA  280
#define GB_H1   294
#define EMS     9
#define H1S     15

// ---------------- device scratch ----------------
__device__ __align__(16) __nv_bfloat16 g_Abf[(size_t)MT*128*KP];
__device__ __align__(16) __nv_bfloat16 g_Bbf[(size_t)VP*KP];
__device__ __align__(16) __nv_bfloat16 g_nbbf[(size_t)256*KP2];
__device__ __align__(16) __nv_bfloat16 g_w1bf[(size_t)896*KP2];
__device__ __align__(16) __nv_bfloat16 g_rnnbf[(size_t)512*KP2];
__device__ __align__(16) __nv_bfloat16 g_emwbf[(size_t)256*KP2];
__device__ __align__(16) __nv_bfloat16 g_E[(size_t)TT*KT*VV];
__device__ float g_rsumP[(size_t)TT*KT*NT2];
__device__ float g_invZ[TT*KT];
__device__ __align__(16) float g_part1[EMZ*500*EHH];
__device__ __align__(16) float g_partx[4*500*4*EHH];
__device__ __align__(16) float g_mapped[500*EHH];
__device__ __align__(16) float g_xz[500*4*EHH];
__device__ __align__(16) float2 g_WhhT2[(EHH/2)*(4*EHH)];
__device__ float g_hbuf[SSRC*256];
__device__ float g_lstm_out[TT*SSRC*EHH];
__device__ float g_base_mu[TT*SSRC*KT];
__device__ float g_base_ls[TT*SSRC*KT];
__device__ float g_etas[SSRC*TT*KT];
__device__ __align__(16) float g_part4[H1Z*BB*THH];
__device__ __align__(16) float g_part5[8*BB*THH];
__device__ __align__(16) float g_h1[BB*THH];
__device__ __align__(16) float g_h2[BB*THH];
__device__ float g_theta[BB*KT];
__device__ float g_wdoc[BB*KT];
__device__ float g_metaT[EHH*KT];
__device__ float g_letaT[EHH*KT];
__device__ float g_mthT[THH*KT];
__device__ float g_lthT[THH*KT];
__device__ float g_w1etaT[KT*THH];
__device__ float g_muRT[KT*KT];
__device__ float g_lsRT[KT*KT];
__device__ int   g_dlist[TT*BB];
__device__ int   g_dcnt[TT];
__device__ float g_pa[KT*TT];
__device__ float g_pnllT[TT*NVTILE];
__device__ float g_pth[BB];
__device__ float g_ppred[BB];
__device__ float g_kleta[1];
// per-source barrier state (LSTM)
__device__ unsigned g_sb_cnt[SSRC*32];
__device__ unsigned g_sb_phase[SSRC*32];

__device__ __forceinline__ float sigm_(float x){ return 1.f/(1.f+expf(-x)); }

__device__ __forceinline__ void srcbar(int s){
    __syncthreads();
    if(threadIdx.x==0){
        __threadfence();
        volatile unsigned* ph=(volatile unsigned*)&g_sb_phase[s*32];
        unsigned p=*ph;
        if(atomicAdd(&g_sb_cnt[s*32],1u)==3u){
            g_sb_cnt[s*32]=0u;
            __threadfence();
            atomicAdd(&g_sb_phase[s*32],1u);
        } else { while(*ph==p){} }
        __threadfence();
    }
    __syncthreads();
}

// ---------------- HMMA / async primitives ----------------
__device__ __forceinline__ void ldsm_x4(uint32_t& r0,uint32_t& r1,uint32_t& r2,uint32_t& r3,uint32_t a){
    asm volatile("ldmatrix.sync.aligned.m8n8.x4.shared.b16 {%0,%1,%2,%3}, [%4];"
                 : "=r"(r0),"=r"(r1),"=r"(r2),"=r"(r3) : "r"(a));
}
__device__ __forceinline__ void mma16816(float* d,const uint32_t* a,const uint32_t* b){
    asm volatile("mma.sync.aligned.m16n8k16.row.col.f32.bf16.bf16.f32 "
        "{%0,%1,%2,%3}, {%4,%5,%6,%7}, {%8,%9}, {%0,%1,%2,%3};"
        : "+f"(d[0]),"+f"(d[1]),"+f"(d[2]),"+f"(d[3])
        : "r"(a[0]),"r"(a[1]),"r"(a[2]),"r"(a[3]), "r"(b[0]),"r"(b[1]));
}
__device__ __forceinline__ void cpasync16(uint32_t dst, const void* src){
    asm volatile("cp.async.cg.shared.global [%0], [%1], 16;" :: "r"(dst), "l"(src));
}
__device__ __forceinline__ void cpcommit(){ asm volatile("cp.async.commit_group;" ::: "memory"); }

// ---- shared 3-stage pipelined NT GEMM body ----
__device__ __forceinline__ void gemm3_body(
    const uint4* __restrict__ Ag, const uint4* __restrict__ Bg,
    int kch, int arow, int brow, int s0, int s1,
    uint8_t* smem, int tid, int wm, int wn, float acc[2][8][4])
{
    const int l=tid&31;
    const int ar_=(l&15), ac_=(l>>4);
    const int br_=(l&7)+((l>>4)&1)*8, bc_=(l>>3)&1;
    const int lrow=tid>>3, lcol=tid&7;
    const uint32_t sbase=(uint32_t)__cvta_generic_to_shared(smem);

    auto issue=[&](int s){
        uint32_t sb=sbase+(uint32_t)(s%3)*32768u;
#pragma unroll
        for(int it=0;it<4;it++){
            int row=lrow+32*it;
            uint32_t off=(uint32_t)row*128u + (uint32_t)((lcol^(row&7))*16);
            cpasync16(sb+off,        &Ag[(size_t)(arow+row)*kch + s*8 + lcol]);
            cpasync16(sb+16384u+off, &Bg[(size_t)(brow+row)*kch + s*8 + lcol]);
        }
        cpcommit();
    };

    issue(s0);
    if(s0+1<s1) issue(s0+1);
    for(int s=s0;s<s1;s++){
        if(s+2<s1){ issue(s+2); asm volatile("cp.async.wait_group 2;" ::: "memory"); }
        else if(s+1<s1){ asm volatile("cp.async.wait_group 1;" ::: "memory"); }
        else { asm volatile("cp.async.wait_group 0;" ::: "memory"); }
        __syncthreads();
        const uint32_t sA=sbase+(uint32_t)(s%3)*32768u;
        const uint32_t sB=sA+16384u;
#pragma unroll
        for(int ks=0;ks<4;ks++){
            uint32_t afr[2][4];
#pragma unroll
            for(int i=0;i<2;i++){
                int row=wm+i*16+ar_;
                int ch=ks*2+ac_;
                ldsm_x4(afr[i][0],afr[i][1],afr[i][2],afr[i][3],
                        sA + row*128 + ((ch^(row&7))*16));
            }
            uint32_t bfr[8][2];
#pragma unroll
            for(int jj=0;jj<4;jj++){
                int row=wn+jj*16+br_;
                int ch=ks*2+bc_;
                uint32_t r0,r1,r2,r3;
                ldsm_x4(r0,r1,r2,r3, sB + row*128 + ((ch^(row&7))*16));
                bfr[jj*2][0]=r0; bfr[jj*2][1]=r1;
                bfr[jj*2+1][0]=r2; bfr[jj*2+1][1]=r3;
            }
#pragma unroll
            for(int i=0;i<2;i++)
#pragma unroll
                for(int j=0;j<8;j++)
                    mma16816(acc[i][j],afr[i],bfr[j]);
        }
        __syncthreads();
    }
}

// ============ mega GEMM: beta + eta_map + h1 ============
__global__ void __launch_bounds__(256,2)
mega_gemm()
{
    extern __shared__ __align__(16) uint8_t smem[];
    const int tid=threadIdx.x, l=tid&31, wid=tid>>5;
    const int wm=(wid&3)*32, wn=(wid>>2)*64;
    float acc[2][8][4];
#pragma unroll
    for(int i=0;i<2;i++)
#pragma unroll
        for(int j=0;j<8;j++)
#pragma unroll
            for(int q=0;q<4;q++) acc[i][j][q]=0.f;

    int bid=blockIdx.x;
    if(bid<GB_BETA){
        const int bn=(bid%NT)*128, bm=(bid/NT)*128;
        gemm3_body((const uint4*)g_Abf,(const uint4*)g_Bbf,40,bm,bn,0,5,
                   smem,tid,wm,wn,acc);
        __nv_bfloat16* E=g_E;
#pragma unroll
        for(int i=0;i<2;i++){
            int r0=bm+wm+i*16+(l>>2);
            int r1=r0+8;
            float s0=0.f,s1=0.f;
#pragma unroll
            for(int j=0;j<8;j++){
                int gn=bn+wn+j*8+2*(l&3);
                bool v=gn<VV;
                float e0=__expf(acc[i][j][0]), e1=__expf(acc[i][j][1]);
                float e2=__expf(acc[i][j][2]), e3=__expf(acc[i][j][3]);
                if(v){
                    __nv_bfloat162 p01, p23;
                    p01.x=__float2bfloat16(e0); p01.y=__float2bfloat16(e1);
                    p23.x=__float2bfloat16(e2); p23.y=__float2bfloat16(e3);
                    if(r0<TT*KT) *(__nv_bfloat162*)(E+(size_t)r0*VV+gn)=p01;
                    if(r1<TT*KT) *(__nv_bfloat162*)(E+(size_t)r1*VV+gn)=p23;
                    s0+=e0+e1; s1+=e2+e3;
                }
            }
            s0+=__shfl_xor_sync(0xffffffffu,s0,1); s0+=__shfl_xor_sync(0xffffffffu,s0,2);
            s1+=__shfl_xor_sync(0xffffffffu,s1,1); s1+=__shfl_xor_sync(0xffffffffu,s1,2);
            if((l&3)==0){
                int slot=(bid%NT)*2+(wid>>2);
                if(r0<TT*KT) g_rsumP[(size_t)r0*NT2+slot]=s0;
                if(r1<TT*KT) g_rsumP[(size_t)r1*NT2+slot]=s1;
            }
        }
    } else if(bid<GB_BETA+GB_ETA){
        int b2=bid-GB_BETA;
        int z=b2/8, r=b2%8;
        int bn=(r%2)*128, bm=(r/2)*128;
        int s0=z*EMS, s1=min(KSTG,s0+EMS);
        gemm3_body((const uint4*)g_rnnbf,(const uint4*)g_emwbf,KCH,bm,bn,s0,s1,
                   smem,tid,wm,wn,acc);
        float* C=g_part1+(size_t)z*500*EHH;
#pragma unroll
        for(int i=0;i<2;i++){
            int r0=bm+wm+i*16+(l>>2);
            int r1=r0+8;
#pragma unroll
            for(int j=0;j<8;j++){
                int gn=bn+wn+j*8+2*(l&3);
                if(gn<EHH){
                    if(r0<500) *(float2*)(C+(size_t)r0*EHH+gn)=make_float2(acc[i][j][0],acc[i][j][1]);
                    if(r1<500) *(float2*)(C+(size_t)r1*EHH+gn)=make_float2(acc[i][j][2],acc[i][j][3]);
                }
            }
        }
    } else {
        int b3=bid-GB_BETA-GB_ETA;
        int z=b3/14, r=b3%14;
        int bn=(r%7)*128, bm=(r/7)*128;
        int s0=z*H1S, s1=min(KSTG,s0+H1S);
        gemm3_body((const uint4*)g_nbbf,(const uint4*)g_w1bf,KCH,bm,bn,s0,s1,
                   smem,tid,wm,wn,acc);
        float* C=g_part4+(size_t)z*BB*THH;
#pragma unroll
        for(int i=0;i<2;i++){
            int r0=bm+wm+i*16+(l>>2);
            int r1=r0+8;
#pragma unroll
            for(int j=0;j<8;j++){
                int gn=bn+wn+j*8+2*(l&3);
                if(gn<THH){
                    if(r0<BB) *(float2*)(C+(size_t)r0*THH+gn)=make_float2(acc[i][j][0],acc[i][j][1]);
                    if(r1<BB) *(float2*)(C+(size_t)r1*THH+gn)=make_float2(acc[i][j][2],acc[i][j][3]);
                }
            }
        }
    }
}

// ---------------- post1: rsum reduce + eta mapped reduce ----------------
__global__ void __launch_bounds__(256) post1_kernel(const float* __restrict__ eta_map_b)
{
    int bid=blockIdx.x;
    const int tid=threadIdx.x;
    if(bid<10){
        int r=bid*256+tid;
        if(r<TT*KT){
            float s=0.f;
            for(int i=0;i<NT2;i++) s+=g_rsumP[(size_t)r*NT2+i];
            g_invZ[r]=1.f/s;
        }
        return;
    }
    bid-=10;
    int i=bid*256+tid;
    if(i>=500*EHH) return;
    float v=0.f;
    for(int z=0;z<EMZ;z++) v+=g_part1[(size_t)z*500*EHH+i];
    g_mapped[i]=v+eta_map_b[i%EHH];
}

// ---------------- mega prep ----------------
__device__ __forceinline__ void conv_seg(const float* __restrict__ src,int rows,int lds,
                                         __nv_bfloat16* __restrict__ dst,int gi)
{
    int r=gi/NG8, c0=(gi%NG8)*8;
    __nv_bfloat16 o[8];
    if(r<rows && c0+7<VV){
        const float* p=src+(size_t)r*lds+c0;
        float2 a=*(const float2*)(p+0);
        float2 b=*(const float2*)(p+2);
        float2 c=*(const float2*)(p+4);
        float2 d=*(const float2*)(p+6);
        o[0]=__float2bfloat16(a.x); o[1]=__float2bfloat16(a.y);
        o[2]=__float2bfloat16(b.x); o[3]=__float2bfloat16(b.y);
        o[4]=__float2bfloat16(c.x); o[5]=__float2bfloat16(c.y);
        o[6]=__float2bfloat16(d.x); o[7]=__float2bfloat16(d.y);
    } else {
#pragma unroll
        for(int q=0;q<8;q++) o[q]=__float2bfloat16(0.f);
    }
    *(uint4*)(dst+(size_t)r*KP2+c0)=*(uint4*)o;
}

__global__ void __launch_bounds__(256) mega_prep(
    const float* __restrict__ mu_q_alpha, const float* __restrict__ rho,
    const float* __restrict__ nbows, const float* __restrict__ W1,
    const float* __restrict__ rnn, const float* __restrict__ emw,
    const float* __restrict__ whh,
    const float* __restrict__ muEta, const float* __restrict__ lsEta,
    const float* __restrict__ muTh, const float* __restrict__ lsTh,
    const float* __restrict__ lsA, const int* __restrict__ times)
{
    int bid=blockIdx.x;
    const int tid=threadIdx.x;
    if(bid<NB_ABF){
        int gi=bid*256+tid;
        int m=gi/40, c0=(gi%40)*8;
        __nv_bfloat16 o[8];
        if(m<TT*KT && c0+8<=RHOD){
            int t=m/KT, k=m%KT;
            const float* p=mu_q_alpha+((size_t)k*TT+t)*RHOD+c0;
            float2 a=*(const float2*)(p+0);
            float2 b=*(const float2*)(p+2);
            float2 c=*(const float2*)(p+4);
            float2 d=*(const float2*)(p+6);
            o[0]=__float2bfloat16(a.x); o[1]=__float2bfloat16(a.y);
            o[2]=__float2bfloat16(b.x); o[3]=__float2bfloat16(b.y);
            o[4]=__float2bfloat16(c.x); o[5]=__float2bfloat16(c.y);
            o[6]=__float2bfloat16(d.x); o[7]=__float2bfloat16(d.y);
        } else {
            int t=m/KT, k=m%KT;
#pragma unroll
            for(int q=0;q<8;q++){
                int r=c0+q;
                float v=(m<TT*KT && r<RHOD)? mu_q_alpha[((size_t)k*TT+t)*RHOD+r] : 0.f;
                o[q]=__float2bfloat16(v);
            }
        }
        *(uint4*)(g_Abf+(size_t)m*KP+c0)=*(uint4*)o;
        return;
    }
    bid-=NB_ABF;
    if(bid<NB_BBF){
        int gi=bid*256+tid;
        int v=gi/40, c0=(gi%40)*8;
        __nv_bfloat16 o[8];
        if(v<VV && c0+8<=RHOD){
            const float* p=rho+(size_t)v*RHOD+c0;
            float2 a=*(const float2*)(p+0);
            float2 b=*(const float2*)(p+2);
            float2 c=*(const float2*)(p+4);
            float2 d=*(const float2*)(p+6);
            o[0]=__float2bfloat16(a.x); o[1]=__float2bfloat16(a.y);
            o[2]=__float2bfloat16(b.x); o[3]=__float2bfloat16(b.y);
            o[4]=__float2bfloat16(c.x); o[5]=__float2bfloat16(c.y);
            o[6]=__float2bfloat16(d.x); o[7]=__float2bfloat16(d.y);
        } else {
#pragma unroll
            for(int q=0;q<8;q++){
                int r=c0+q;
                float x=(v<VV && r<RHOD)? rho[(size_t)v*RHOD+r] : 0.f;
                o[q]=__float2bfloat16(x);
            }
        }
        *(uint4*)(g_Bbf+(size_t)v*KP+c0)=*(uint4*)o;
        return;
    }
    bid-=NB_BBF;
    if(bid<NB_CN){ conv_seg(nbows,256,VV, g_nbbf, bid*256+tid); return; }
    bid-=NB_CN;
    if(bid<NB_CW){ conv_seg(W1,THH,VV+KT, g_w1bf, bid*256+tid); return; }
    bid-=NB_CW;
    if(bid<NB_CR){ conv_seg(rnn,500,VV, g_rnnbf, bid*256+tid); return; }
    bid-=NB_CR;
    if(bid<NB_CE){ conv_seg(emw,EHH,VV, g_emwbf, bid*256+tid); return; }
    bid-=NB_CE;
    if(bid<NB_WH){
        int i=bid*256+tid;
        if(i<(EHH/2)*(4*EHH)){
            int k2=i/(4*EHH), j=i%(4*EHH);
            float2 w;
            w.x=whh[(size_t)j*EHH+2*k2];
            w.y=whh[(size_t)j*EHH+2*k2+1];
            g_WhhT2[i]=w;
        }
        return;
    }
    bid-=NB_WH;
    if(bid<NB_HD){
        int i=bid*256+tid;
        if(i<KT*EHH){
            int k=i/EHH, j=i%EHH;
            g_metaT[j*KT+k]=muEta[(size_t)k*(EHH+KT)+j];
            g_letaT[j*KT+k]=lsEta[(size_t)k*(EHH+KT)+j];
        }
        if(i<KT*THH){
            int k=i/THH, j=i%THH;
            g_mthT[j*KT+k]=muTh[(size_t)k*THH+j];
            g_lthT[j*KT+k]=lsTh[(size_t)k*THH+j];
            g_w1etaT[i]=W1[(size_t)j*(VV+KT)+VV+k];
        }
        if(i<KT*KT){
            int k2=i/KT, k=i%KT;
            g_muRT[i]=muEta[(size_t)k*(EHH+KT)+EHH+k2];
            g_lsRT[i]=lsEta[(size_t)k*(EHH+KT)+EHH+k2];
        }
        return;
    }
    bid-=NB_HD;
    if(bid<NB_DL){
        int t=tid;
        if(t<TT){
            int cnt=0;
            for(int b=0;b<BB;b++)
                if(times[b]==t) g_dlist[t*BB + (cnt++)]=b;
            g_dcnt[t]=cnt;
        }
        return;
    }
    bid-=NB_DL;
    {
        __shared__ float red[256];
        int b=bid; int t=b%TT;
        const float* mup=mu_q_alpha+(size_t)b*RHOD;
        const float* lsp=lsA+(size_t)b*RHOD;
        const float* mpv=mu_q_alpha+(size_t)(b-1)*RHOD;
        float s=0.f;
        for(int r=tid;r<RHOD;r+=256){
            float m=mup[r], l=lsp[r];
            if(t==0) s += (expf(l)+m*m)/(1.f+EPSF) - 1.f - l;
            else { float d=m-mpv[r]; s += (expf(l)+d*d)/(DELTAF+EPSF) - 1.f + LOG_DELTA_F - l; }
        }
        red[tid]=s; __syncthreads();
        for(int off=128;off>0;off>>=1){ if(tid<off) red[tid]+=red[tid+off]; __syncthreads(); }
        if(tid==0) g_pa[b]=0.5f*red[0];
    }
}

// ============ fp32 NT SGEMM (xz and h2) ============
template<int OP>
__global__ void __launch_bounds__(256)
sgemm128(int M,int N,int Kd,
         const float* __restrict__ A,int lda,
         const float* __restrict__ B,int ldb,
         float* __restrict__ C,int ldc,
         const float* __restrict__ bias1,const float* __restrict__ bias2)
{
    __shared__ float As[8][128];
    __shared__ float Bs[8][128];
    const int tid=threadIdx.x;
    const int bm=blockIdx.y*128, bn=blockIdx.x*128;
    int k0=0,k1=Kd;
    const int nz=gridDim.z;
    if(nz>1){
        int kChunk=((Kd + nz*8 - 1)/(nz*8))*8;
        k0=blockIdx.z*kChunk; k1=min(Kd,k0+kChunk);
        C += (size_t)blockIdx.z*(size_t)M*(size_t)ldc;
    }
    const int lr=tid>>1, kq=(tid&1)*4;
    const int tx=tid&15, ty=tid>>4;
    float acc[8][8];
#pragma unroll
    for(int i=0;i<8;i++)
#pragma unroll
        for(int j=0;j<8;j++) acc[i][j]=0.f;

    const bool aval=(bm+lr)<M, bval=(bn+lr)<N;
    const float* Ap=A+(size_t)(bm+lr)*lda;
    const float* Bp=B+(size_t)(bn+lr)*ldb;

    for(int kb=k0;kb<k1;kb+=8){
        float4 av=aval? *(const float4*)(Ap+kb+kq) : make_float4(0.f,0.f,0.f,0.f);
        float4 bv=bval? *(const float4*)(Bp+kb+kq) : make_float4(0.f,0.f,0.f,0.f);
        __syncthreads();
        As[kq+0][lr]=av.x; As[kq+1][lr]=av.y; As[kq+2][lr]=av.z; As[kq+3][lr]=av.w;
        Bs[kq+0][lr]=bv.x; Bs[kq+1][lr]=bv.y; Bs[kq+2][lr]=bv.z; Bs[kq+3][lr]=bv.w;
        __syncthreads();
#pragma unroll
        for(int kk=0;kk<8;kk++){
            float ar[8],br[8];
#pragma unroll
            for(int i=0;i<8;i++) ar[i]=As[kk][ty*8+i];
#pragma unroll
            for(int j=0;j<8;j++) br[j]=Bs[kk][tx*8+j];
#pragma unroll
            for(int i=0;i<8;i++)
#pragma unroll
                for(int j=0;j<8;j++) acc[i][j]=fmaf(ar[i],br[j],acc[i][j]);
        }
    }
    const bool raw=(nz>1);
#pragma unroll
    for(int i=0;i<8;i++){
        int gm=bm+ty*8+i; if(gm>=M) continue;
#pragma unroll
        for(int j=0;j<8;j++){
            int gn=bn+tx*8+j; if(gn>=N) continue;
            float v=acc[i][j];
            if(!raw){
                if(bias1) v+=bias1[gn];
                if(bias2) v+=bias2[gn];
                if(OP==1) v=fmaxf(v,0.f);
                else if(OP==2) v=expf(v);
            }
            C[(size_t)gm*ldc+gn]=v;
        }
    }
}

__global__ void reduce_split(const float* __restrict__ parts,int splits,int total,int N,
                             const float* __restrict__ bias1,const float* __restrict__ bias2,
                             int op, float* __restrict__ out)
{
    int i=blockIdx.x*blockDim.x+threadIdx.x;
    if(i>=total) return;
    float v=0.f;
    for(int z=0;z<splits;z++) v+=parts[(size_t)z*total+i];
    if(bias1) v+=bias1[i%N];
    if(bias2) v+=bias2[i%N];
    if(op==1) v=fmaxf(v,0.f);
    out[i]=v;
}

// ---------------- LSTM: 4 blocks per source, sense barriers ----------------
__global__ void __launch_bounds__(256) lstm40_kernel()
{
    __shared__ __align__(8) float hsm[256];
    __shared__ float zsh[256];
    const int tid=threadIdx.x;
    const int s=blockIdx.x/4, q=blockIdx.x%4, n0=q*50;
    float c=0.f;
    if(tid<50) g_hbuf[s*256+n0+tid]=0.f;
    srcbar(s);
    for(int t=0;t<TT;t++){
        if(tid<200) hsm[tid]=g_hbuf[s*256+tid];
        __syncthreads();
        if(tid<200){
            int gate=tid/50, cell=tid%50;
            int j=gate*200+n0+cell;
            float acc=g_xz[((size_t)s*TT+t)*(4*EHH)+j];
#pragma unroll 4
            for(int k2=0;k2<EHH/2;k2++){
                float2 w=g_WhhT2[k2*(4*EHH)+j];
                float2 hv=*(const float2*)(hsm+2*k2);
                acc=fmaf(hv.x,w.x,acc);
                acc=fmaf(hv.y,w.y,acc);
            }
            zsh[tid]=acc;
        }
        __syncthreads();
        if(tid<50){
            float ig=sigm_(zsh[tid]);
            float fg=sigm_(zsh[50+tid]);
            float gg=tanhf(zsh[100+tid]);
            float og=sigm_(zsh[150+tid]);
            c=fg*c+ig*gg;
            float h=og*tanhf(c);
            g_hbuf[s*256+n0+tid]=h;
            g_lstm_out[((size_t)t*SSRC+s)*EHH+n0+tid]=h;
        }
        srcbar(s);
    }
}

// ---------------- eta base ----------------
__global__ void eta_base_kernel()
{
    int i=blockIdx.x*blockDim.x+threadIdx.x;
    if(i>=TT*SSRC*KT) return;
    int k=i%KT; int ts=i/KT;
    const float* h=g_lstm_out+(size_t)ts*EHH;
    float am=0.f, al=0.f;
    for(int j=0;j<EHH;j++){
        float hv=h[j];
        am=fmaf(hv,g_metaT[j*KT+k],am);
        al=fmaf(hv,g_letaT[j*KT+k],al);
    }
    g_base_mu[i]=am; g_base_ls[i]=al;
}

// ---------------- eta recurrence + kl_eta ----------------
__global__ void __launch_bounds__(512) eta_rec_kernel(const float* __restrict__ mub,
                                                      const float* __restrict__ lsb)
{
    __shared__ float eprev[SSRC*KT];
    __shared__ float red[512];
    const int tid=threadIdx.x;
    const int s=tid/KT, k=tid%KT;
    const bool act = tid < SSRC*KT;
    float kl=0.f;
    if(act){
        float m=g_base_mu[tid]+mub[k];
        float l=g_base_ls[tid]+lsb[k];
        kl += (expf(l)+m*m)/(1.f+EPSF) - 1.f - l;
        eprev[tid]=m;
        g_etas[((size_t)s*TT+0)*KT+k]=m;
    }
    __syncthreads();
    for(int t=1;t<TT;t++){
        float m=0.f;
        if(act){
            m=g_base_mu[(size_t)t*SSRC*KT+tid]+mub[k];
            float l=g_base_ls[(size_t)t*SSRC*KT+tid]+lsb[k];
            const float* er=eprev+s*KT;
#pragma unroll
            for(int k2=0;k2<KT;k2++){
                float e=er[k2];
                m=fmaf(e,g_muRT[k2*KT+k],m);
                l=fmaf(e,g_lsRT[k2*KT+k],l);
            }
            l=fminf(fmaxf(l,-10.f),10.f);
            float d=m-eprev[tid];
            kl += (expf(l)+d*d)/(DELTAF+EPSF) - 1.f + LOG_DELTA_F - l;
        }
        __syncthreads();
        if(act){ eprev[tid]=m; g_etas[((size_t)s*TT+t)*KT+k]=m; }
        __syncthreads();
    }
    red[tid]=kl; __syncthreads();
    for(int off=256;off>0;off>>=1){ if(tid<off) red[tid]+=red[tid+off]; __syncthreads(); }
    if(tid==0) g_kleta[0]=0.5f*red[0];
}

// ---------------- h1 epilogue ----------------
__global__ void h1_epilogue(const float* __restrict__ b1,
                            const int* __restrict__ sources,const int* __restrict__ times)
{
    int i=blockIdx.x*blockDim.x+threadIdx.x;
    if(i>=BB*THH) return;
    int b=i/THH, j=i%THH;
    float v=0.f;
    for(int z=0;z<H1Z;z++) v+=g_part4[(size_t)z*BB*THH+i];
    v+=b1[j];
    const float* e=g_etas+((size_t)sources[b]*TT+times[b])*KT;
#pragma unroll
    for(int k=0;k<KT;k++) v=fmaf(e[k], g_w1etaT[k*THH+j], v);
    g_h1[i]=fmaxf(v,0.f);
}

// ---------------- fused theta ----------------
__global__ void __launch_bounds__(256) theta_fused(
    const float* __restrict__ mub,const float* __restrict__ lsb,
    const float* __restrict__ clsW,const float* __restrict__ clsb,
    const int* __restrict__ sources,const int* __restrict__ times)
{
    __shared__ float h[THH];
    __shared__ float pm[KT][5], pl[KT][5];
    __shared__ float muv[KT], lsv[KT], th[KT], es[KT];
    const int b=blockIdx.x, tid=threadIdx.x;
    for(int j=tid;j<THH;j+=256) h[j]=g_h2[(size_t)b*THH+j];
    __syncthreads();
    if(tid<250){
        int k=tid/5, g=tid%5;
        float am=0.f, al=0.f;
        for(int j=g*160;j<(g+1)*160;j++){
            float hv=h[j];
            am=fmaf(hv,g_mthT[j*KT+k],am);
            al=fmaf(hv,g_lthT[j*KT+k],al);
        }
        pm[k][g]=am; pl[k][g]=al;
    }
    __syncthreads();
    const int t=times[b], src=sources[b];
    if(tid<KT){
        float am=mub[tid], al=lsb[tid];
#pragma unroll
        for(int g=0;g<5;g++){ am+=pm[tid][g]; al+=pl[tid][g]; }
        al=fminf(fmaxf(al,-10.f),10.f);
        muv[tid]=am; lsv[tid]=al;
        es[tid]=g_etas[((size_t)src*TT+t)*KT+tid];
    }
    __syncthreads();
    if(tid==0){
        float mx=-1e30f;
        for(int k=0;k<KT;k++) mx=fmaxf(mx,muv[k]);
        float Z=0.f;
        for(int k=0;k<KT;k++){ float e=expf(muv[k]-mx); th[k]=e; Z+=e; }
        float iZ=1.f/Z;
        float kl=0.f;
        for(int k=0;k<KT;k++){
            th[k]*=iZ;
            float d=muv[k]-es[k];
            kl += (expf(lsv[k])+d*d)/(1.f+EPSF)-1.f-lsv[k];
        }
        g_pth[b]=0.5f*kl;
        float lg[SSRC], mxl=-1e30f;
        for(int i=0;i<SSRC;i++){
            float a=clsb[i];
            for(int k=0;k<KT;k++) a=fmaf(th[k],clsW[i*KT+k],a);
            lg[i]=a; mxl=fmaxf(mxl,a);
        }
        float se=0.f;
        for(int i=0;i<SSRC;i++) se+=expf(lg[i]-mxl);
        g_ppred[b]=mxl+logf(se)-lg[src];
    }
    __syncthreads();
    if(tid<KT){
        g_theta[(size_t)b*KT+tid]=th[tid];
        g_wdoc[(size_t)b*KT+tid]=th[tid]*g_invZ[t*KT+tid];
    }
}

// ---------------- NLL ----------------
__global__ void __launch_bounds__(256) nll2_kernel(const float* __restrict__ bows)
{
    const int t=blockIdx.x, vt=blockIdx.y, tid=threadIdx.x;
    __shared__ float ws[32][KT];
    __shared__ int   dls[32];
    __shared__ float red[256];
    const int cnt=g_dcnt[t];
    float s=0.f;
    for(int d0=0; d0<cnt; d0+=32){
        int ch=min(32,cnt-d0);
        __syncthreads();
        for(int i=tid;i<ch*KT;i+=256){
            int d=i/KT, k=i%KT;
            int b=g_dlist[t*BB+d0+d];
            ws[d][k]=g_wdoc[(size_t)b*KT+k];
            if(k==0) dls[d]=b;
        }
        __syncthreads();
        for(int vi=0;vi<4;vi++){
            int v=vt*1024+vi*256+tid;
            if(v>=VV) break;
            float e[KT];
            const __nv_bfloat16* Ep=g_E+(size_t)t*KT*VV+v;
#pragma unroll
            for(int k=0;k<KT;k++) e[k]=__bfloat162float(Ep[(size_t)k*VV]);
            for(int d=0;d<ch;d++){
                float mix=0.f;
#pragma unroll
                for(int k=0;k<KT;k++) mix=fmaf(ws[d][k],e[k],mix);
                s=fmaf(__logf(mix), bows[(size_t)dls[d]*VV+v], s);
            }
        }
    }
    red[tid]=s; __syncthreads();
    for(int off=128;off>0;off>>=1){ if(tid<off) red[tid]+=red[tid+off]; __syncthreads(); }
    if(tid==0) g_pnllT[t*NVTILE+vt]=red[0];
}

// ---------------- final combine ----------------
__global__ void __launch_bounds__(256) final_kernel(const void* __restrict__ ndocs_ptr,
                                                    float* __restrict__ out)
{
    __shared__ float red[256];
    const int tid=threadIdx.x;
    float sa=0.f;
    for(int i=tid;i<KT*TT;i+=256) sa+=g_pa[i];
    red[tid]=sa; __syncthreads();
    for(int off=128;off>0;off>>=1){ if(tid<off) red[tid]+=red[tid+off]; __syncthreads(); }
    float kl_alpha=red[0]; __syncthreads();

    float sl=0.f;
    for(int i=tid;i<TT*NVTILE;i+=256) sl+=g_pnllT[i];
    red[tid]=sl; __syncthreads();
    for(int off=128;off>0;off>>=1){ if(tid<off) red[tid]+=red[tid+off]; __syncthreads(); }
    float sum_ll=red[0]; __syncthreads();

    red[tid]=g_pth[tid]; __syncthreads();
    for(int off=128;off>0;off>>=1){ if(tid<off) red[tid]+=red[tid+off]; __syncthreads(); }
    float sum_th=red[0]; __syncthreads();

    red[tid]=g_ppred[tid]; __syncthreads();
    for(int off=128;off>0;off>>=1){ if(tid<off) red[tid]+=red[tid+off]; __syncthreads(); }
    float sum_pred=red[0]; __syncthreads();

    if(tid==0){
        int v0=*(const int*)ndocs_ptr;
        float nd;
        if(v0>0 && v0<(1<<30)) nd=(float)v0;
        else nd=*(const float*)ndocs_ptr;
        float coeff=nd/(float)BB;
        float nll=-sum_ll*coeff;
        float kl_eta=g_kleta[0];
        float kl_theta=sum_th*coeff;
        float pred=sum_pred*coeff;
        float nelbo=nll+kl_alpha+kl_eta+kl_theta+pred;
        out[0]=nelbo; out[1]=nll; out[2]=kl_alpha;
        out[3]=kl_eta; out[4]=kl_theta; out[5]=pred;
    }
}

// ---------------- launcher ----------------
extern "C" void kernel_launch(void* const* d_in, const int* in_sizes, int n_in,
                              void* d_out, int out_size)
{
    const float* bows      =(const float*)d_in[1];
    const float* nbows     =(const float*)d_in[2];
    const int*   times     =(const int*)  d_in[3];
    const int*   sources   =(const int*)  d_in[4];
    const float* rnn_inp   =(const float*)d_in[5];
    const void*  num_docs  =               d_in[6];
    const float* mu_q_alpha=(const float*)d_in[7];
    const float* ls_q_alpha=(const float*)d_in[8];
    const float* rho_W     =(const float*)d_in[9];
    const float* W1        =(const float*)d_in[10];
    const float* b1        =(const float*)d_in[11];
    const float* W2        =(const float*)d_in[12];
    const float* b2        =(const float*)d_in[13];
    const float* mu_th_W   =(const float*)d_in[14];
    const float* mu_th_b   =(const float*)d_in[15];
    const float* ls_th_W   =(const float*)d_in[16];
    const float* ls_th_b   =(const float*)d_in[17];
    const float* eta_map_W =(const float*)d_in[18];
    const float* eta_map_b =(const float*)d_in[19];
    const float* lstm_Wih  =(const float*)d_in[20];
    const float* lstm_Whh  =(const float*)d_in[21];
    const float* lstm_bih  =(const float*)d_in[22];
    const float* lstm_bhh  =(const float*)d_in[23];
    const float* mu_eta_W  =(const float*)d_in[24];
    const float* mu_eta_b  =(const float*)d_in[25];
    const float* ls_eta_W  =(const float*)d_in[26];
    const float* ls_eta_b  =(const float*)d_in[27];
    const float* cls_W     =(const float*)d_in[28];
    const float* cls_b     =(const float*)d_in[29];
    float* out=(float*)d_out;

    float *partx,*mapped,*xz,*part5,*h1,*h2;
    cudaGetSymbolAddress((void**)&partx,g_partx);
    cudaGetSymbolAddress((void**)&mapped,g_mapped);
    cudaGetSymbolAddress((void**)&xz,g_xz);
    cudaGetSymbolAddress((void**)&part5,g_part5);
    cudaGetSymbolAddress((void**)&h1,g_h1);
    cudaGetSymbolAddress((void**)&h2,g_h2);

    static int init_done=0;
    if(!init_done){
        cudaFuncSetAttribute(mega_gemm, cudaFuncAttributeMaxDynamicSharedMemorySize, 98304);
        init_done=1;
    }

    // 1: elementwise prep (+ kl_alpha, doclist)
    {
        int grid=NB_ABF+NB_BBF+NB_CN+NB_CW+NB_CR+NB_CE+NB_WH+NB_HD+NB_DL+NB_KA;
        mega_prep<<<grid,256>>>(mu_q_alpha,rho_W,nbows,W1,rnn_inp,eta_map_W,lstm_Whh,
                                mu_eta_W,ls_eta_W,mu_th_W,ls_th_W,ls_q_alpha,times);
    }
    // 2: all three HMMA GEMMs in one launch
    mega_gemm<<<GB_BETA+GB_ETA+GB_H1,256,98304>>>();
    // 3: rsum reduce + eta mapped reduce
    post1_kernel<<<10+(500*EHH+255)/256,256>>>(eta_map_b);
    // 4-5: xz = mapped @ Wih^T + biases
    {
        dim3 g((4*EHH+127)/128,(500+127)/128,4);
        sgemm128<0><<<g,256>>>(500,4*EHH,EHH, mapped,EHH, lstm_Wih,EHH,
                               partx,4*EHH, nullptr,nullptr);
        reduce_split<<<(500*4*EHH+255)/256,256>>>(partx,4,500*4*EHH,4*EHH, lstm_bih,lstm_bhh,0, xz);
    }
    // 6-8: lstm (40 blocks) -> eta base -> eta recurrence
    lstm40_kernel<<<40,256>>>();
    eta_base_kernel<<<(TT*SSRC*KT+255)/256,256>>>();
    eta_rec_kernel<<<1,512>>>(mu_eta_b, ls_eta_b);
    // 9: h1 epilogue
    h1_epilogue<<<(BB*THH+255)/256,256>>>(b1, sources, times);
    // 10-11: h2
    {
        dim3 g((THH+127)/128,(BB+127)/128,8);
        sgemm128<0><<<g,256>>>(BB,THH,THH, h1,THH, W2,THH,
                               part5,THH, nullptr,nullptr);
        reduce_split<<<(BB*THH+255)/256,256>>>(part5,8,BB*THH,THH, b2,nullptr,1, h2);
    }
    // 12: theta fused
    theta_fused<<<BB,256>>>(mu_th_b, ls_th_b, cls_W, cls_b, sources, times);
    // 13: NLL
    {
        dim3 g(TT,NVTILE,1);
        nll2_kernel<<<g,256>>>(bows);
    }
    // 14: combine
    final_kernel<<<1,256>>>(num_docs, out);
    (void)in_sizes; (void)n_in; (void)out_size;
}

// round 16
// speedup vs baseline: 1.9523x; 1.9523x over previous
#include <cuda_runtime.h>
#include <cuda_bf16.h>
#include <math.h>
#include <stdint.h>

#define KT   50
#define TT   50
#define RHOD 300
#define KP   320
#define VV   20000
#define KP2  20032
#define KCH  2504
#define KSTG 313
#define VP   20096
#define NT   157
#define NT2  (2*NT)
#define MT   20
#define THH  800
#define EHH  200
#define SSRC 10
#define BB   256
#define H1Z  21
#define EMZ  35
#define DELTAF 0.005f
#define LOG_DELTA_F (-5.2983173665480363f)
#define EPSF 1e-6f
#define NVTILE 20
#define NG8  (KP2/8)

// mega_prep block ranges
#define NB_ABF 400
#define NB_BBF 3140
#define NB_CN  2504
#define NB_CW  8764
#define NB_CR  5008
#define NB_CE  2504
#define NB_WH  157      // 50*800 float4 slots / 256
#define NB_HD  157
#define NB_KA  2500

// mega_gemm ranges
#define GB_BETA 3140
#define GB_ETA  280
#define GB_H1   294
#define EMS     9
#define H1S     15

// ---------------- device scratch ----------------
__device__ __align__(16) __nv_bfloat16 g_Abf[(size_t)MT*128*KP];
__device__ __align__(16) __nv_bfloat16 g_Bbf[(size_t)VP*KP];
__device__ __align__(16) __nv_bfloat16 g_nbbf[(size_t)256*KP2];
__device__ __align__(16) __nv_bfloat16 g_w1bf[(size_t)896*KP2];
__device__ __align__(16) __nv_bfloat16 g_rnnbf[(size_t)512*KP2];
__device__ __align__(16) __nv_bfloat16 g_emwbf[(size_t)256*KP2];
__device__ __align__(16) __nv_bfloat16 g_E[(size_t)TT*KT*VV];
__device__ float g_rsumP[(size_t)TT*KT*NT2];
__device__ float g_invZ[TT*KT];
__device__ __align__(16) float g_part1[EMZ*500*EHH];
__device__ __align__(16) float g_partx[4*500*4*EHH];
__device__ __align__(16) float g_mapped[500*EHH];
__device__ __align__(16) float g_xz[500*4*EHH];
__device__ __align__(16) float4 g_WhhT4[(EHH/4)*(4*EHH)];
__device__ float g_lstm_out[TT*SSRC*EHH];
__device__ float g_base_mu[TT*SSRC*KT];
__device__ float g_base_ls[TT*SSRC*KT];
__device__ float g_etas[SSRC*TT*KT];
__device__ __align__(16) float g_part4[H1Z*BB*THH];
__device__ __align__(16) float g_part5[8*BB*THH];
__device__ __align__(16) float g_h1[BB*THH];
__device__ __align__(16) float g_h2[BB*THH];
__device__ float g_theta[BB*KT];
__device__ float g_wdoc[BB*KT];
__device__ float g_metaT[EHH*KT];
__device__ float g_letaT[EHH*KT];
__device__ float g_mthT[THH*KT];
__device__ float g_lthT[THH*KT];
__device__ float g_w1etaT[KT*THH];
__device__ float g_muRT[KT*KT];
__device__ float g_lsRT[KT*KT];
__device__ int   g_dlist[TT*BB];
__device__ int   g_dcnt[TT];
__device__ float g_pa[KT*TT];
__device__ float g_pnllT[TT*NVTILE];
__device__ float g_pth[BB];
__device__ float g_ppred[BB];
__device__ float g_kleta[1];

__device__ __forceinline__ float sigm_(float x){ return 1.f/(1.f+expf(-x)); }

// ---------------- HMMA / async primitives ----------------
__device__ __forceinline__ void ldsm_x4(uint32_t& r0,uint32_t& r1,uint32_t& r2,uint32_t& r3,uint32_t a){
    asm volatile("ldmatrix.sync.aligned.m8n8.x4.shared.b16 {%0,%1,%2,%3}, [%4];"
                 : "=r"(r0),"=r"(r1),"=r"(r2),"=r"(r3) : "r"(a));
}
__device__ __forceinline__ void mma16816(float* d,const uint32_t* a,const uint32_t* b){
    asm volatile("mma.sync.aligned.m16n8k16.row.col.f32.bf16.bf16.f32 "
        "{%0,%1,%2,%3}, {%4,%5,%6,%7}, {%8,%9}, {%0,%1,%2,%3};"
        : "+f"(d[0]),"+f"(d[1]),"+f"(d[2]),"+f"(d[3])
        : "r"(a[0]),"r"(a[1]),"r"(a[2]),"r"(a[3]), "r"(b[0]),"r"(b[1]));
}
__device__ __forceinline__ void cpasync16(uint32_t dst, const void* src){
    asm volatile("cp.async.cg.shared.global [%0], [%1], 16;" :: "r"(dst), "l"(src));
}
__device__ __forceinline__ void cpcommit(){ asm volatile("cp.async.commit_group;" ::: "memory"); }

// ---- shared 3-stage pipelined NT GEMM body ----
__device__ __forceinline__ void gemm3_body(
    const uint4* __restrict__ Ag, const uint4* __restrict__ Bg,
    int kch, int arow, int brow, int s0, int s1,
    uint8_t* smem, int tid, int wm, int wn, float acc[2][8][4])
{
    const int l=tid&31;
    const int ar_=(l&15), ac_=(l>>4);
    const int br_=(l&7)+((l>>4)&1)*8, bc_=(l>>3)&1;
    const int lrow=tid>>3, lcol=tid&7;
    const uint32_t sbase=(uint32_t)__cvta_generic_to_shared(smem);

    auto issue=[&](int s){
        uint32_t sb=sbase+(uint32_t)(s%3)*32768u;
#pragma unroll
        for(int it=0;it<4;it++){
            int row=lrow+32*it;
            uint32_t off=(uint32_t)row*128u + (uint32_t)((lcol^(row&7))*16);
            cpasync16(sb+off,        &Ag[(size_t)(arow+row)*kch + s*8 + lcol]);
            cpasync16(sb+16384u+off, &Bg[(size_t)(brow+row)*kch + s*8 + lcol]);
        }
        cpcommit();
    };

    issue(s0);
    if(s0+1<s1) issue(s0+1);
    for(int s=s0;s<s1;s++){
        if(s+2<s1){ issue(s+2); asm volatile("cp.async.wait_group 2;" ::: "memory"); }
        else if(s+1<s1){ asm volatile("cp.async.wait_group 1;" ::: "memory"); }
        else { asm volatile("cp.async.wait_group 0;" ::: "memory"); }
        __syncthreads();
        const uint32_t sA=sbase+(uint32_t)(s%3)*32768u;
        const uint32_t sB=sA+16384u;
#pragma unroll
        for(int ks=0;ks<4;ks++){
            uint32_t afr[2][4];
#pragma unroll
            for(int i=0;i<2;i++){
                int row=wm+i*16+ar_;
                int ch=ks*2+ac_;
                ldsm_x4(afr[i][0],afr[i][1],afr[i][2],afr[i][3],
                        sA + row*128 + ((ch^(row&7))*16));
            }
            uint32_t bfr[8][2];
#pragma unroll
            for(int jj=0;jj<4;jj++){
                int row=wn+jj*16+br_;
                int ch=ks*2+bc_;
                uint32_t r0,r1,r2,r3;
                ldsm_x4(r0,r1,r2,r3, sB + row*128 + ((ch^(row&7))*16));
                bfr[jj*2][0]=r0; bfr[jj*2][1]=r1;
                bfr[jj*2+1][0]=r2; bfr[jj*2+1][1]=r3;
            }
#pragma unroll
            for(int i=0;i<2;i++)
#pragma unroll
                for(int j=0;j<8;j++)
                    mma16816(acc[i][j],afr[i],bfr[j]);
        }
        __syncthreads();
    }
}

// ============ mega GEMM: beta + eta_map + h1 ============
__global__ void __launch_bounds__(256,2)
mega_gemm()
{
    extern __shared__ __align__(16) uint8_t smem[];
    const int tid=threadIdx.x, l=tid&31, wid=tid>>5;
    const int wm=(wid&3)*32, wn=(wid>>2)*64;
    float acc[2][8][4];
#pragma unroll
    for(int i=0;i<2;i++)
#pragma unroll
        for(int j=0;j<8;j++)
#pragma unroll
            for(int q=0;q<4;q++) acc[i][j][q]=0.f;

    int bid=blockIdx.x;
    if(bid<GB_BETA){
        const int bn=(bid%NT)*128, bm=(bid/NT)*128;
        gemm3_body((const uint4*)g_Abf,(const uint4*)g_Bbf,40,bm,bn,0,5,
                   smem,tid,wm,wn,acc);
        __nv_bfloat16* E=g_E;
#pragma unroll
        for(int i=0;i<2;i++){
            int r0=bm+wm+i*16+(l>>2);
            int r1=r0+8;
            float s0=0.f,s1=0.f;
#pragma unroll
            for(int j=0;j<8;j++){
                int gn=bn+wn+j*8+2*(l&3);
                bool v=gn<VV;
                float e0=__expf(acc[i][j][0]), e1=__expf(acc[i][j][1]);
                float e2=__expf(acc[i][j][2]), e3=__expf(acc[i][j][3]);
                if(v){
                    __nv_bfloat162 p01, p23;
                    p01.x=__float2bfloat16(e0); p01.y=__float2bfloat16(e1);
                    p23.x=__float2bfloat16(e2); p23.y=__float2bfloat16(e3);
                    if(r0<TT*KT) *(__nv_bfloat162*)(E+(size_t)r0*VV+gn)=p01;
                    if(r1<TT*KT) *(__nv_bfloat162*)(E+(size_t)r1*VV+gn)=p23;
                    s0+=e0+e1; s1+=e2+e3;
                }
            }
            s0+=__shfl_xor_sync(0xffffffffu,s0,1); s0+=__shfl_xor_sync(0xffffffffu,s0,2);
            s1+=__shfl_xor_sync(0xffffffffu,s1,1); s1+=__shfl_xor_sync(0xffffffffu,s1,2);
            if((l&3)==0){
                int slot=(bid%NT)*2+(wid>>2);
                if(r0<TT*KT) g_rsumP[(size_t)r0*NT2+slot]=s0;
                if(r1<TT*KT) g_rsumP[(size_t)r1*NT2+slot]=s1;
            }
        }
    } else if(bid<GB_BETA+GB_ETA){
        int b2=bid-GB_BETA;
        int z=b2/8, r=b2%8;
        int bn=(r%2)*128, bm=(r/2)*128;
        int s0=z*EMS, s1=min(KSTG,s0+EMS);
        gemm3_body((const uint4*)g_rnnbf,(const uint4*)g_emwbf,KCH,bm,bn,s0,s1,
                   smem,tid,wm,wn,acc);
        float* C=g_part1+(size_t)z*500*EHH;
#pragma unroll
        for(int i=0;i<2;i++){
            int r0=bm+wm+i*16+(l>>2);
            int r1=r0+8;
#pragma unroll
            for(int j=0;j<8;j++){
                int gn=bn+wn+j*8+2*(l&3);
                if(gn<EHH){
                    if(r0<500) *(float2*)(C+(size_t)r0*EHH+gn)=make_float2(acc[i][j][0],acc[i][j][1]);
                    if(r1<500) *(float2*)(C+(size_t)r1*EHH+gn)=make_float2(acc[i][j][2],acc[i][j][3]);
                }
            }
        }
    } else {
        int b3=bid-GB_BETA-GB_ETA;
        int z=b3/14, r=b3%14;
        int bn=(r%7)*128, bm=(r/7)*128;
        int s0=z*H1S, s1=min(KSTG,s0+H1S);
        gemm3_body((const uint4*)g_nbbf,(const uint4*)g_w1bf,KCH,bm,bn,s0,s1,
                   smem,tid,wm,wn,acc);
        float* C=g_part4+(size_t)z*BB*THH;
#pragma unroll
        for(int i=0;i<2;i++){
            int r0=bm+wm+i*16+(l>>2);
            int r1=r0+8;
#pragma unroll
            for(int j=0;j<8;j++){
                int gn=bn+wn+j*8+2*(l&3);
                if(gn<THH){
                    if(r0<BB) *(float2*)(C+(size_t)r0*THH+gn)=make_float2(acc[i][j][0],acc[i][j][1]);
                    if(r1<BB) *(float2*)(C+(size_t)r1*THH+gn)=make_float2(acc[i][j][2],acc[i][j][3]);
                }
            }
        }
    }
}

// ---------------- post1: rsum reduce + eta mapped reduce ----------------
__global__ void __launch_bounds__(256) post1_kernel(const float* __restrict__ eta_map_b)
{
    int bid=blockIdx.x;
    const int tid=threadIdx.x;
    if(bid<10){
        int r=bid*256+tid;
        if(r<TT*KT){
            float s=0.f;
            for(int i=0;i<NT2;i++) s+=g_rsumP[(size_t)r*NT2+i];
            g_invZ[r]=1.f/s;
        }
        return;
    }
    bid-=10;
    int i=bid*256+tid;
    if(i>=500*EHH) return;
    float v=0.f;
    for(int z=0;z<EMZ;z++) v+=g_part1[(size_t)z*500*EHH+i];
    g_mapped[i]=v+eta_map_b[i%EHH];
}

// ---------------- mega prep ----------------
__device__ __forceinline__ void conv_seg(const float* __restrict__ src,int rows,int lds,
                                         __nv_bfloat16* __restrict__ dst,int gi)
{
    int r=gi/NG8, c0=(gi%NG8)*8;
    __nv_bfloat16 o[8];
    if(r<rows && c0+7<VV){
        const float* p=src+(size_t)r*lds+c0;
        float2 a=*(const float2*)(p+0);
        float2 b=*(const float2*)(p+2);
        float2 c=*(const float2*)(p+4);
        float2 d=*(const float2*)(p+6);
        o[0]=__float2bfloat16(a.x); o[1]=__float2bfloat16(a.y);
        o[2]=__float2bfloat16(b.x); o[3]=__float2bfloat16(b.y);
        o[4]=__float2bfloat16(c.x); o[5]=__float2bfloat16(c.y);
        o[6]=__float2bfloat16(d.x); o[7]=__float2bfloat16(d.y);
    } else {
#pragma unroll
        for(int q=0;q<8;q++) o[q]=__float2bfloat16(0.f);
    }
    *(uint4*)(dst+(size_t)r*KP2+c0)=*(uint4*)o;
}

__global__ void __launch_bounds__(256) mega_prep(
    const float* __restrict__ mu_q_alpha, const float* __restrict__ rho,
    const float* __restrict__ nbows, const float* __restrict__ W1,
    const float* __restrict__ rnn, const float* __restrict__ emw,
    const float* __restrict__ whh,
    const float* __restrict__ muEta, const float* __restrict__ lsEta,
    const float* __restrict__ muTh, const float* __restrict__ lsTh,
    const float* __restrict__ lsA)
{
    int bid=blockIdx.x;
    const int tid=threadIdx.x;
    if(bid<NB_ABF){
        int gi=bid*256+tid;
        int m=gi/40, c0=(gi%40)*8;
        __nv_bfloat16 o[8];
        if(m<TT*KT && c0+8<=RHOD){
            int t=m/KT, k=m%KT;
            const float* p=mu_q_alpha+((size_t)k*TT+t)*RHOD+c0;
            float2 a=*(const float2*)(p+0);
            float2 b=*(const float2*)(p+2);
            float2 c=*(const float2*)(p+4);
            float2 d=*(const float2*)(p+6);
            o[0]=__float2bfloat16(a.x); o[1]=__float2bfloat16(a.y);
            o[2]=__float2bfloat16(b.x); o[3]=__float2bfloat16(b.y);
            o[4]=__float2bfloat16(c.x); o[5]=__float2bfloat16(c.y);
            o[6]=__float2bfloat16(d.x); o[7]=__float2bfloat16(d.y);
        } else {
            int t=m/KT, k=m%KT;
#pragma unroll
            for(int q=0;q<8;q++){
                int r=c0+q;
                float v=(m<TT*KT && r<RHOD)? mu_q_alpha[((size_t)k*TT+t)*RHOD+r] : 0.f;
                o[q]=__float2bfloat16(v);
            }
        }
        *(uint4*)(g_Abf+(size_t)m*KP+c0)=*(uint4*)o;
        return;
    }
    bid-=NB_ABF;
    if(bid<NB_BBF){
        int gi=bid*256+tid;
        int v=gi/40, c0=(gi%40)*8;
        __nv_bfloat16 o[8];
        if(v<VV && c0+8<=RHOD){
            const float* p=rho+(size_t)v*RHOD+c0;
            float2 a=*(const float2*)(p+0);
            float2 b=*(const float2*)(p+2);
            float2 c=*(const float2*)(p+4);
            float2 d=*(const float2*)(p+6);
            o[0]=__float2bfloat16(a.x); o[1]=__float2bfloat16(a.y);
            o[2]=__float2bfloat16(b.x); o[3]=__float2bfloat16(b.y);
            o[4]=__float2bfloat16(c.x); o[5]=__float2bfloat16(c.y);
            o[6]=__float2bfloat16(d.x); o[7]=__float2bfloat16(d.y);
        } else {
#pragma unroll
            for(int q=0;q<8;q++){
                int r=c0+q;
                float x=(v<VV && r<RHOD)? rho[(size_t)v*RHOD+r] : 0.f;
                o[q]=__float2bfloat16(x);
            }
        }
        *(uint4*)(g_Bbf+(size_t)v*KP+c0)=*(uint4*)o;
        return;
    }
    bid-=NB_BBF;
    if(bid<NB_CN){ conv_seg(nbows,256,VV, g_nbbf, bid*256+tid); return; }
    bid-=NB_CN;
    if(bid<NB_CW){ conv_seg(W1,THH,VV+KT, g_w1bf, bid*256+tid); return; }
    bid-=NB_CW;
    if(bid<NB_CR){ conv_seg(rnn,500,VV, g_rnnbf, bid*256+tid); return; }
    bid-=NB_CR;
    if(bid<NB_CE){ conv_seg(emw,EHH,VV, g_emwbf, bid*256+tid); return; }
    bid-=NB_CE;
    if(bid<NB_WH){
        int i=bid*256+tid;
        if(i<(EHH/4)*(4*EHH)){
            int k4=i/(4*EHH), j=i%(4*EHH);
            float4 w;
            w.x=whh[(size_t)j*EHH+4*k4+0];
            w.y=whh[(size_t)j*EHH+4*k4+1];
            w.z=whh[(size_t)j*EHH+4*k4+2];
            w.w=whh[(size_t)j*EHH+4*k4+3];
            g_WhhT4[i]=w;
        }
        return;
    }
    bid-=NB_WH;
    if(bid<NB_HD){
        int i=bid*256+tid;
        if(i<KT*EHH){
            int k=i/EHH, j=i%EHH;
            g_metaT[j*KT+k]=muEta[(size_t)k*(EHH+KT)+j];
            g_letaT[j*KT+k]=lsEta[(size_t)k*(EHH+KT)+j];
        }
        if(i<KT*THH){
            int k=i/THH, j=i%THH;
            g_mthT[j*KT+k]=muTh[(size_t)k*THH+j];
            g_lthT[j*KT+k]=lsTh[(size_t)k*THH+j];
            g_w1etaT[i]=W1[(size_t)j*(VV+KT)+VV+k];
        }
        if(i<KT*KT){
            int k2=i/KT, k=i%KT;
            g_muRT[i]=muEta[(size_t)k*(EHH+KT)+EHH+k2];
            g_lsRT[i]=lsEta[(size_t)k*(EHH+KT)+EHH+k2];
        }
        return;
    }
    bid-=NB_HD;
    {
        __shared__ float red[256];
        int b=bid; int t=b%TT;
        const float* mup=mu_q_alpha+(size_t)b*RHOD;
        const float* lsp=lsA+(size_t)b*RHOD;
        const float* mpv=mu_q_alpha+(size_t)(b-1)*RHOD;
        float s=0.f;
        for(int r=tid;r<RHOD;r+=256){
            float m=mup[r], l=lsp[r];
            if(t==0) s += (expf(l)+m*m)/(1.f+EPSF) - 1.f - l;
            else { float d=m-mpv[r]; s += (expf(l)+d*d)/(DELTAF+EPSF) - 1.f + LOG_DELTA_F - l; }
        }
        red[tid]=s; __syncthreads();
        for(int off=128;off>0;off>>=1){ if(tid<off) red[tid]+=red[tid+off]; __syncthreads(); }
        if(tid==0) g_pa[b]=0.5f*red[0];
    }
}

// ============ fp32 NT SGEMM (xz and h2) ============
template<int OP>
__global__ void __launch_bounds__(256)
sgemm128(int M,int N,int Kd,
         const float* __restrict__ A,int lda,
         const float* __restrict__ B,int ldb,
         float* __restrict__ C,int ldc,
         const float* __restrict__ bias1,const float* __restrict__ bias2)
{
    __shared__ float As[8][128];
    __shared__ float Bs[8][128];
    const int tid=threadIdx.x;
    const int bm=blockIdx.y*128, bn=blockIdx.x*128;
    int k0=0,k1=Kd;
    const int nz=gridDim.z;
    if(nz>1){
        int kChunk=((Kd + nz*8 - 1)/(nz*8))*8;
        k0=blockIdx.z*kChunk; k1=min(Kd,k0+kChunk);
        C += (size_t)blockIdx.z*(size_t)M*(size_t)ldc;
    }
    const int lr=tid>>1, kq=(tid&1)*4;
    const int tx=tid&15, ty=tid>>4;
    float acc[8][8];
#pragma unroll
    for(int i=0;i<8;i++)
#pragma unroll
        for(int j=0;j<8;j++) acc[i][j]=0.f;

    const bool aval=(bm+lr)<M, bval=(bn+lr)<N;
    const float* Ap=A+(size_t)(bm+lr)*lda;
    const float* Bp=B+(size_t)(bn+lr)*ldb;

    for(int kb=k0;kb<k1;kb+=8){
        float4 av=aval? *(const float4*)(Ap+kb+kq) : make_float4(0.f,0.f,0.f,0.f);
        float4 bv=bval? *(const float4*)(Bp+kb+kq) : make_float4(0.f,0.f,0.f,0.f);
        __syncthreads();
        As[kq+0][lr]=av.x; As[kq+1][lr]=av.y; As[kq+2][lr]=av.z; As[kq+3][lr]=av.w;
        Bs[kq+0][lr]=bv.x; Bs[kq+1][lr]=bv.y; Bs[kq+2][lr]=bv.z; Bs[kq+3][lr]=bv.w;
        __syncthreads();
#pragma unroll
        for(int kk=0;kk<8;kk++){
            float ar[8],br[8];
#pragma unroll
            for(int i=0;i<8;i++) ar[i]=As[kk][ty*8+i];
#pragma unroll
            for(int j=0;j<8;j++) br[j]=Bs[kk][tx*8+j];
#pragma unroll
            for(int i=0;i<8;i++)
#pragma unroll
                for(int j=0;j<8;j++) acc[i][j]=fmaf(ar[i],br[j],acc[i][j]);
        }
    }
    const bool raw=(nz>1);
#pragma unroll
    for(int i=0;i<8;i++){
        int gm=bm+ty*8+i; if(gm>=M) continue;
#pragma unroll
        for(int j=0;j<8;j++){
            int gn=bn+tx*8+j; if(gn>=N) continue;
            float v=acc[i][j];
            if(!raw){
                if(bias1) v+=bias1[gn];
                if(bias2) v+=bias2[gn];
                if(OP==1) v=fmaxf(v,0.f);
                else if(OP==2) v=expf(v);
            }
            C[(size_t)gm*ldc+gn]=v;
        }
    }
}

__global__ void reduce_split(const float* __restrict__ parts,int splits,int total,int N,
                             const float* __restrict__ bias1,const float* __restrict__ bias2,
                             int op, float* __restrict__ out)
{
    int i=blockIdx.x*blockDim.x+threadIdx.x;
    if(i>=total) return;
    float v=0.f;
    for(int z=0;z<splits;z++) v+=parts[(size_t)z*total+i];
    if(bias1) v+=bias1[i%N];
    if(bias2) v+=bias2[i%N];
    if(op==1) v=fmaxf(v,0.f);
    out[i]=v;
}

// ---------------- LSTM: one block per source, float4 weights ----------------
__global__ void __launch_bounds__(4*EHH) lstm_kernel()
{
    __shared__ __align__(16) float hsm[EHH];
    __shared__ float zsm[4*EHH];
    const int s=blockIdx.x, j=threadIdx.x;
    float c=0.f;
    if(j<EHH) hsm[j]=0.f;
    __syncthreads();
    for(int t=0;t<TT;t++){
        float acc=g_xz[((size_t)s*TT+t)*(4*EHH)+j];
#pragma unroll 5
        for(int k4=0;k4<EHH/4;k4++){
            float4 w=g_WhhT4[k4*(4*EHH)+j];
            float4 hv=*(const float4*)(hsm+4*k4);
            acc=fmaf(hv.x,w.x,acc);
            acc=fmaf(hv.y,w.y,acc);
            acc=fmaf(hv.z,w.z,acc);
            acc=fmaf(hv.w,w.w,acc);
        }
        zsm[j]=acc;
        __syncthreads();
        if(j<EHH){
            float ig=sigm_(zsm[j]), fg=sigm_(zsm[EHH+j]);
            float gg=tanhf(zsm[2*EHH+j]), og=sigm_(zsm[3*EHH+j]);
            c=fg*c+ig*gg;
            float h=og*tanhf(c);
            hsm[j]=h;
            g_lstm_out[((size_t)t*SSRC+s)*EHH+j]=h;
        }
        __syncthreads();
    }
}

// ---------------- eta base ----------------
__global__ void eta_base_kernel()
{
    int i=blockIdx.x*blockDim.x+threadIdx.x;
    if(i>=TT*SSRC*KT) return;
    int k=i%KT; int ts=i/KT;
    const float* h=g_lstm_out+(size_t)ts*EHH;
    float am=0.f, al=0.f;
    for(int j=0;j<EHH;j++){
        float hv=h[j];
        am=fmaf(hv,g_metaT[j*KT+k],am);
        al=fmaf(hv,g_letaT[j*KT+k],al);
    }
    g_base_mu[i]=am; g_base_ls[i]=al;
}

// ---------------- eta recurrence + kl_eta ----------------
__global__ void __launch_bounds__(512) eta_rec_kernel(const float* __restrict__ mub,
                                                      const float* __restrict__ lsb)
{
    __shared__ float eprev[SSRC*KT];
    __shared__ float red[512];
    const int tid=threadIdx.x;
    const int s=tid/KT, k=tid%KT;
    const bool act = tid < SSRC*KT;
    float kl=0.f;
    if(act){
        float m=g_base_mu[tid]+mub[k];
        float l=g_base_ls[tid]+lsb[k];
        kl += (expf(l)+m*m)/(1.f+EPSF) - 1.f - l;
        eprev[tid]=m;
        g_etas[((size_t)s*TT+0)*KT+k]=m;
    }
    __syncthreads();
    for(int t=1;t<TT;t++){
        float m=0.f;
        if(act){
            m=g_base_mu[(size_t)t*SSRC*KT+tid]+mub[k];
            float l=g_base_ls[(size_t)t*SSRC*KT+tid]+lsb[k];
            const float* er=eprev+s*KT;
#pragma unroll
            for(int k2=0;k2<KT;k2++){
                float e=er[k2];
                m=fmaf(e,g_muRT[k2*KT+k],m);
                l=fmaf(e,g_lsRT[k2*KT+k],l);
            }
            l=fminf(fmaxf(l,-10.f),10.f);
            float d=m-eprev[tid];
            kl += (expf(l)+d*d)/(DELTAF+EPSF) - 1.f + LOG_DELTA_F - l;
        }
        __syncthreads();
        if(act){ eprev[tid]=m; g_etas[((size_t)s*TT+t)*KT+k]=m; }
        __syncthreads();
    }
    red[tid]=kl; __syncthreads();
    for(int off=256;off>0;off>>=1){ if(tid<off) red[tid]+=red[tid+off]; __syncthreads(); }
    if(tid==0) g_kleta[0]=0.5f*red[0];
}

// ---------------- h1 epilogue ----------------
__global__ void h1_epilogue(const float* __restrict__ b1,
                            const int* __restrict__ sources,const int* __restrict__ times)
{
    int i=blockIdx.x*blockDim.x+threadIdx.x;
    if(i>=BB*THH) return;
    int b=i/THH, j=i%THH;
    float v=0.f;
    for(int z=0;z<H1Z;z++) v+=g_part4[(size_t)z*BB*THH+i];
    v+=b1[j];
    const float* e=g_etas+((size_t)sources[b]*TT+times[b])*KT;
#pragma unroll
    for(int k=0;k<KT;k++) v=fmaf(e[k], g_w1etaT[k*THH+j], v);
    g_h1[i]=fmaxf(v,0.f);
}

// ---------------- fused theta ----------------
__global__ void __launch_bounds__(256) theta_fused(
    const float* __restrict__ mub,const float* __restrict__ lsb,
    const float* __restrict__ clsW,const float* __restrict__ clsb,
    const int* __restrict__ sources,const int* __restrict__ times)
{
    __shared__ float h[THH];
    __shared__ float pm[KT][5], pl[KT][5];
    __shared__ float muv[KT], lsv[KT], th[KT], es[KT];
    const int b=blockIdx.x, tid=threadIdx.x;
    for(int j=tid;j<THH;j+=256) h[j]=g_h2[(size_t)b*THH+j];
    __syncthreads();
    if(tid<250){
        int k=tid/5, g=tid%5;
        float am=0.f, al=0.f;
        for(int j=g*160;j<(g+1)*160;j++){
            float hv=h[j];
            am=fmaf(hv,g_mthT[j*KT+k],am);
            al=fmaf(hv,g_lthT[j*KT+k],al);
        }
        pm[k][g]=am; pl[k][g]=al;
    }
    __syncthreads();
    const int t=times[b], src=sources[b];
    if(tid<KT){
        float am=mub[tid], al=lsb[tid];
#pragma unroll
        for(int g=0;g<5;g++){ am+=pm[tid][g]; al+=pl[tid][g]; }
        al=fminf(fmaxf(al,-10.f),10.f);
        muv[tid]=am; lsv[tid]=al;
        es[tid]=g_etas[((size_t)src*TT+t)*KT+tid];
    }
    __syncthreads();
    if(tid==0){
        float mx=-1e30f;
        for(int k=0;k<KT;k++) mx=fmaxf(mx,muv[k]);
        float Z=0.f;
        for(int k=0;k<KT;k++){ float e=expf(muv[k]-mx); th[k]=e; Z+=e; }
        float iZ=1.f/Z;
        float kl=0.f;
        for(int k=0;k<KT;k++){
            th[k]*=iZ;
            float d=muv[k]-es[k];
            kl += (expf(lsv[k])+d*d)/(1.f+EPSF)-1.f-lsv[k];
        }
        g_pth[b]=0.5f*kl;
        float lg[SSRC], mxl=-1e30f;
        for(int i=0;i<SSRC;i++){
            float a=clsb[i];
            for(int k=0;k<KT;k++) a=fmaf(th[k],clsW[i*KT+k],a);
            lg[i]=a; mxl=fmaxf(mxl,a);
        }
        float se=0.f;
        for(int i=0;i<SSRC;i++) se+=expf(lg[i]-mxl);
        g_ppred[b]=mxl+logf(se)-lg[src];
    }
    __syncthreads();
    if(tid<KT){
        g_theta[(size_t)b*KT+tid]=th[tid];
        g_wdoc[(size_t)b*KT+tid]=th[tid]*g_invZ[t*KT+tid];
    }
    if(b==0 && tid==255){
        int cnt[TT];
        for(int tt=0;tt<TT;tt++) cnt[tt]=0;
        for(int bb=0;bb<BB;bb++){
            int td=times[bb];
            g_dlist[td*BB + cnt[td]]=bb;
            cnt[td]++;
        }
        for(int tt=0;tt<TT;tt++) g_dcnt[tt]=cnt[tt];
    }
}

// ---------------- NLL ----------------
__global__ void __launch_bounds__(256) nll2_kernel(const float* __restrict__ bows)
{
    const int t=blockIdx.x, vt=blockIdx.y, tid=threadIdx.x;
    __shared__ float ws[32][KT];
    __shared__ int   dls[32];
    __shared__ float red[256];
    const int cnt=g_dcnt[t];
    float s=0.f;
    for(int d0=0; d0<cnt; d0+=32){
        int ch=min(32,cnt-d0);
        __syncthreads();
        for(int i=tid;i<ch*KT;i+=256){
            int d=i/KT, k=i%KT;
            int b=g_dlist[t*BB+d0+d];
            ws[d][k]=g_wdoc[(size_t)b*KT+k];
            if(k==0) dls[d]=b;
        }
        __syncthreads();
        for(int vi=0;vi<4;vi++){
            int v=vt*1024+vi*256+tid;
            if(v>=VV) break;
            float e[KT];
            const __nv_bfloat16* Ep=g_E+(size_t)t*KT*VV+v;
#pragma unroll
            for(int k=0;k<KT;k++) e[k]=__bfloat162float(Ep[(size_t)k*VV]);
            for(int d=0;d<ch;d++){
                float mix=0.f;
#pragma unroll
                for(int k=0;k<KT;k++) mix=fmaf(ws[d][k],e[k],mix);
                s=fmaf(__logf(mix), bows[(size_t)dls[d]*VV+v], s);
            }
        }
    }
    red[tid]=s; __syncthreads();
    for(int off=128;off>0;off>>=1){ if(tid<off) red[tid]+=red[tid+off]; __syncthreads(); }
    if(tid==0) g_pnllT[t*NVTILE+vt]=red[0];
}

// ---------------- final combine ----------------
__global__ void __launch_bounds__(256) final_kernel(const void* __restrict__ ndocs_ptr,
                                                    float* __restrict__ out)
{
    __shared__ float red[256];
    const int tid=threadIdx.x;
    float sa=0.f;
    for(int i=tid;i<KT*TT;i+=256) sa+=g_pa[i];
    red[tid]=sa; __syncthreads();
    for(int off=128;off>0;off>>=1){ if(tid<off) red[tid]+=red[tid+off]; __syncthreads(); }
    float kl_alpha=red[0]; __syncthreads();

    float sl=0.f;
    for(int i=tid;i<TT*NVTILE;i+=256) sl+=g_pnllT[i];
    red[tid]=sl; __syncthreads();
    for(int off=128;off>0;off>>=1){ if(tid<off) red[tid]+=red[tid+off]; __syncthreads(); }
    float sum_ll=red[0]; __syncthreads();

    red[tid]=g_pth[tid]; __syncthreads();
    for(int off=128;off>0;off>>=1){ if(tid<off) red[tid]+=red[tid+off]; __syncthreads(); }
    float sum_th=red[0]; __syncthreads();

    red[tid]=g_ppred[tid]; __syncthreads();
    for(int off=128;off>0;off>>=1){ if(tid<off) red[tid]+=red[tid+off]; __syncthreads(); }
    float sum_pred=red[0]; __syncthreads();

    if(tid==0){
        int v0=*(const int*)ndocs_ptr;
        float nd;
        if(v0>0 && v0<(1<<30)) nd=(float)v0;
        else nd=*(const float*)ndocs_ptr;
        float coeff=nd/(float)BB;
        float nll=-sum_ll*coeff;
        float kl_eta=g_kleta[0];
        float kl_theta=sum_th*coeff;
        float pred=sum_pred*coeff;
        float nelbo=nll+kl_alpha+kl_eta+kl_theta+pred;
        out[0]=nelbo; out[1]=nll; out[2]=kl_alpha;
        out[3]=kl_eta; out[4]=kl_theta; out[5]=pred;
    }
}

// ---------------- launcher ----------------
extern "C" void kernel_launch(void* const* d_in, const int* in_sizes, int n_in,
                              void* d_out, int out_size)
{
    const float* bows      =(const float*)d_in[1];
    const float* nbows     =(const float*)d_in[2];
    const int*   times     =(const int*)  d_in[3];
    const int*   sources   =(const int*)  d_in[4];
    const float* rnn_inp   =(const float*)d_in[5];
    const void*  num_docs  =               d_in[6];
    const float* mu_q_alpha=(const float*)d_in[7];
    const float* ls_q_alpha=(const float*)d_in[8];
    const float* rho_W     =(const float*)d_in[9];
    const float* W1        =(const float*)d_in[10];
    const float* b1        =(const float*)d_in[11];
    const float* W2        =(const float*)d_in[12];
    const float* b2        =(const float*)d_in[13];
    const float* mu_th_W   =(const float*)d_in[14];
    const float* mu_th_b   =(const float*)d_in[15];
    const float* ls_th_W   =(const float*)d_in[16];
    const float* ls_th_b   =(const float*)d_in[17];
    const float* eta_map_W =(const float*)d_in[18];
    const float* eta_map_b =(const float*)d_in[19];
    const float* lstm_Wih  =(const float*)d_in[20];
    const float* lstm_Whh  =(const float*)d_in[21];
    const float* lstm_bih  =(const float*)d_in[22];
    const float* lstm_bhh  =(const float*)d_in[23];
    const float* mu_eta_W  =(const float*)d_in[24];
    const float* mu_eta_b  =(const float*)d_in[25];
    const float* ls_eta_W  =(const float*)d_in[26];
    const float* ls_eta_b  =(const float*)d_in[27];
    const float* cls_W     =(const float*)d_in[28];
    const float* cls_b     =(const float*)d_in[29];
    float* out=(float*)d_out;

    float *partx,*mapped,*xz,*part5,*h1,*h2;
    cudaGetSymbolAddress((void**)&partx,g_partx);
    cudaGetSymbolAddress((void**)&mapped,g_mapped);
    cudaGetSymbolAddress((void**)&xz,g_xz);
    cudaGetSymbolAddress((void**)&part5,g_part5);
    cudaGetSymbolAddress((void**)&h1,g_h1);
    cudaGetSymbolAddress((void**)&h2,g_h2);

    static int init_done=0;
    if(!init_done){
        cudaFuncSetAttribute(mega_gemm, cudaFuncAttributeMaxDynamicSharedMemorySize, 98304);
        init_done=1;
    }

    // 1: elementwise prep (+ kl_alpha)
    {
        int grid=NB_ABF+NB_BBF+NB_CN+NB_CW+NB_CR+NB_CE+NB_WH+NB_HD+NB_KA;
        mega_prep<<<grid,256>>>(mu_q_alpha,rho_W,nbows,W1,rnn_inp,eta_map_W,lstm_Whh,
                                mu_eta_W,ls_eta_W,mu_th_W,ls_th_W,ls_q_alpha);
    }
    // 2: all three HMMA GEMMs in one launch
    mega_gemm<<<GB_BETA+GB_ETA+GB_H1,256,98304>>>();
    // 3: rsum reduce + eta mapped reduce
    post1_kernel<<<10+(500*EHH+255)/256,256>>>(eta_map_b);
    // 4-5: xz = mapped @ Wih^T + biases
    {
        dim3 g((4*EHH+127)/128,(500+127)/128,4);
        sgemm128<0><<<g,256>>>(500,4*EHH,EHH, mapped,EHH, lstm_Wih,EHH,
                               partx,4*EHH, nullptr,nullptr);
        reduce_split<<<(500*4*EHH+255)/256,256>>>(partx,4,500*4*EHH,4*EHH, lstm_bih,lstm_bhh,0, xz);
    }
    // 6-8: lstm -> eta base -> eta recurrence
    lstm_kernel<<<SSRC,4*EHH>>>();
    eta_base_kernel<<<(TT*SSRC*KT+255)/256,256>>>();
    eta_rec_kernel<<<1,512>>>(mu_eta_b, ls_eta_b);
    // 9: h1 epilogue
    h1_epilogue<<<(BB*THH+255)/256,256>>>(b1, sources, times);
    // 10-11: h2
    {
        dim3 g((THH+127)/128,(BB+127)/128,8);
        sgemm128<0><<<g,256>>>(BB,THH,THH, h1,THH, W2,THH,
                               part5,THH, nullptr,nullptr);
        reduce_split<<<(BB*THH+255)/256,256>>>(part5,8,BB*THH,THH, b2,nullptr,1, h2);
    }
    // 12: theta fused
    theta_fused<<<BB,256>>>(mu_th_b, ls_th_b, cls_W, cls_b, sources, times);
    // 13: NLL
    {
        dim3 g(TT,NVTILE,1);
        nll2_kernel<<<g,256>>>(bows);
    }
    // 14: combine
    final_kernel<<<1,256>>>(num_docs, out);
    (void)in_sizes; (void)n_in; (void)out_size;
}